// round 13
// baseline (speedup 1.0000x reference)
#include <cuda_runtime.h>
#include <cuda_fp16.h>
#include <math.h>
#include <cstdint>

typedef unsigned long long ull;

// Problem constants
#define B_    4
#define C_    64
#define H_    128
#define W_    128
#define HW_   (H_*W_)
#define OFFC_ 32
#define K2_   9
#define OCOFF 27

// ---------------- scratch ----------------
__device__ int    g_idx[B_ * K2_ * HW_];   // packed clamped corners
__device__ uint4  g_wts[B_ * K2_ * HW_];   // bilinear weights as dup'd half2 x4
__device__ __half g_xth[B_ * HW_ * C_];    // x in NHWC fp16: [b][y][x][c]
// W^T as f16x2 pairs (single fp16): [k][o][36 stride, 32 pairs used]
__device__ uint32_t g_wb[K2_ * C_ * 36];

// ---------------- helpers ----------------
__device__ __forceinline__ uint32_t smem_u32(const void* p) {
    uint32_t a;
    asm("{ .reg .u64 t; cvta.to.shared.u64 t, %1; cvt.u32.u64 %0, t; }" : "=r"(a) : "l"(p));
    return a;
}
__device__ __forceinline__ void ffma2(ull& d, ull a, ull b) {
    asm("fma.rn.f32x2 %0, %1, %2, %0;" : "+l"(d) : "l"(a), "l"(b));
}
__device__ __forceinline__ ull dup2(float s) {
    ull d;
    asm("mov.b64 %0, {%1, %1};" : "=l"(d) : "f"(s));
    return d;
}
__device__ __forceinline__ void mma_f16(float4& d,
                                        uint32_t a0, uint32_t a1, uint32_t a2, uint32_t a3,
                                        uint32_t b0, uint32_t b1) {
    asm volatile(
        "mma.sync.aligned.m16n8k16.row.col.f32.f16.f16.f32 "
        "{%0,%1,%2,%3}, {%4,%5,%6,%7}, {%8,%9}, {%0,%1,%2,%3};"
        : "+f"(d.x), "+f"(d.y), "+f"(d.z), "+f"(d.w)
        : "r"(a0), "r"(a1), "r"(a2), "r"(a3), "r"(b0), "r"(b1));
}
#define LDSM4(r0, r1, r2, r3, addr)                                           \
    asm volatile("ldmatrix.sync.aligned.m8n8.x4.shared.b16 {%0,%1,%2,%3}, [%4];" \
                 : "=r"(r0), "=r"(r1), "=r"(r2), "=r"(r3) : "r"(addr))
__device__ __forceinline__ __half2 u2h(uint32_t u) {
    return *reinterpret_cast<__half2*>(&u);
}
__device__ __forceinline__ uint32_t h2u(__half2 h) {
    return *reinterpret_cast<uint32_t*>(&h);
}

// ---------------- Fused prep kernel ----------------
// blocks [0,512)   : x NCHW -> NHWC fp16, one (b,y) row each, 256 thr
// blocks [512,768) : offset conv + descriptors, TWO (b,y) rows each (128 thr/row)
// blocks [768,840) : weight -> fp16 pairs [k][o][pair]  (72 * 256 = 18432 elems)
#define PREP_NHWC_BLKS 512
#define PREP_OFF_BLKS  256
#define PREP_W_BLKS    72
#define PREP_TOTAL     (PREP_NHWC_BLKS + PREP_OFF_BLKS + PREP_W_BLKS)

__global__ __launch_bounds__(256) void prep_kernel(
    const float* __restrict__ x,             // [B,64,H,W]
    const float* __restrict__ offset_feat,   // [B,32,H,W]
    const float* __restrict__ w_off,         // [27,32,3,3]
    const float* __restrict__ b_off,         // [27]
    const float* __restrict__ weight)        // [64,64,3,3]
{
    __shared__ __align__(16) char sraw[33024];
    __shared__ __align__(16) float s_boff[28];

    const int blk = blockIdx.x;
    const int tid = threadIdx.x;

    if (blk < PREP_NHWC_BLKS) {
        // ---------------- NHWC transpose ----------------
        float* st = (float*)sraw;                 // [64][129]
        const int y = blk & (H_ - 1);
        const int b = blk >> 7;

        const float* src = x + ((size_t)b * C_ * H_ + y) * W_;
#pragma unroll
        for (int i = 0; i < 8; i++) {
            int idx = tid + i * 256;
            int c   = idx >> 5;
            int x4  = idx & 31;
            float4 v = __ldg((const float4*)(src + (size_t)c * HW_) + x4);
            float* d = st + c * 129 + x4 * 4;
            d[0] = v.x; d[1] = v.y; d[2] = v.z; d[3] = v.w;
        }
        __syncthreads();

        __half* dst = g_xth + ((size_t)(b * H_ + y) * W_) * C_;
#pragma unroll
        for (int i = 0; i < 8; i++) {
            int idx = tid + i * 256;
            int px  = idx >> 4;
            int cq  = idx & 15;
            float v0 = st[(cq * 4 + 0) * 129 + px];
            float v1 = st[(cq * 4 + 1) * 129 + px];
            float v2 = st[(cq * 4 + 2) * 129 + px];
            float v3 = st[(cq * 4 + 3) * 129 + px];
            uint2 o2;
            o2.x = h2u(__floats2half2_rn(v0, v1));
            o2.y = h2u(__floats2half2_rn(v2, v3));
            *(uint2*)(dst + (size_t)px * C_ + cq * 4) = o2;
        }
    } else if (blk < PREP_NHWC_BLKS + PREP_OFF_BLKS) {
        // ---------------- offset conv + descriptors (2 rows/block) ----------------
        float* s_w = (float*)sraw;                // [288][28]

        for (int i = tid; i < OCOFF * 288; i += 256) {
            int oc = i / 288;
            int r  = i % 288;
            s_w[r * 28 + oc] = w_off[i];
        }
        if (tid < 28) s_boff[tid] = (tid < OCOFF) ? b_off[tid] : 0.f;
        __syncthreads();

        const int r2 = (blk - PREP_NHWC_BLKS) * 2 + (tid >> 7);  // global row id
        const int y  = r2 & (H_ - 1);
        const int b  = r2 >> 7;
        const int xx = tid & 127;

        ull acc2[14];
#pragma unroll
        for (int j = 0; j < 14; j++) acc2[j] = ((const ull*)s_boff)[j];

        const float* fbase = offset_feat + (size_t)b * OFFC_ * HW_;

#pragma unroll
        for (int ky = 0; ky < 3; ky++) {
            const int iy = y - 1 + ky;
            const bool vy = ((unsigned)iy < (unsigned)H_);
#pragma unroll
            for (int kx = 0; kx < 3; kx++) {
                const int ix = xx - 1 + kx;
                const bool v = vy && ((unsigned)ix < (unsigned)W_);
                const int tap = ky * 3 + kx;
                const float* ip = fbase + iy * W_ + ix;
#pragma unroll 4
                for (int c = 0; c < OFFC_; c++) {
                    float vv = v ? __ldg(ip + c * HW_) : 0.f;
                    ull v2 = dup2(vv);
                    const ulonglong2* wp = (const ulonglong2*)(s_w + (c * 9 + tap) * 28);
#pragma unroll
                    for (int j = 0; j < 7; j++) {
                        ulonglong2 ww = wp[j];
                        ffma2(acc2[2 * j],     ww.x, v2);
                        ffma2(acc2[2 * j + 1], ww.y, v2);
                    }
                }
            }
        }

        float acc[28];
#pragma unroll
        for (int j = 0; j < 14; j++) {
            asm("mov.b64 {%0, %1}, %2;" : "=f"(acc[2 * j]), "=f"(acc[2 * j + 1]) : "l"(acc2[j]));
        }

#pragma unroll
        for (int k = 0; k < K2_; k++) {
            float dy = acc[2 * k];
            float dx = acc[2 * k + 1];
            float m  = 1.f / (1.f + __expf(-acc[18 + k]));

            float py = (float)(y - 1 + (k / 3)) + dy;
            float px = (float)(xx - 1 + (k % 3)) + dx;
            float y0f = floorf(py), x0f = floorf(px);
            float wy1 = py - y0f,   wx1 = px - x0f;
            float wy0 = 1.f - wy1,  wx0 = 1.f - wx1;
            int y0 = (int)y0f, x0 = (int)x0f;
            int y1 = y0 + 1,   x1 = x0 + 1;

            bool vy0 = ((unsigned)y0 < (unsigned)H_);
            bool vy1 = ((unsigned)y1 < (unsigned)H_);
            bool vx0 = ((unsigned)x0 < (unsigned)W_);
            bool vx1 = ((unsigned)x1 < (unsigned)W_);

            float w00 = wy0 * wx0 * m * (float)(vy0 && vx0);
            float w01 = wy0 * wx1 * m * (float)(vy0 && vx1);
            float w10 = wy1 * wx0 * m * (float)(vy1 && vx0);
            float w11 = wy1 * wx1 * m * (float)(vy1 && vx1);

            int y0c = min(max(y0, 0), H_ - 1);
            int y1c = min(max(y1, 0), H_ - 1);
            int x0c = min(max(x0, 0), W_ - 1);
            int x1c = min(max(x1, 0), W_ - 1);

            int base = ((b * K2_ + k) * H_ + y) * W_ + xx;
            g_idx[base] = (y0c << 24) | (y1c << 16) | (x0c << 8) | x1c;
            uint4 wq;
            wq.x = h2u(__float2half2_rn(w00));
            wq.y = h2u(__float2half2_rn(w01));
            wq.z = h2u(__float2half2_rn(w10));
            wq.w = h2u(__float2half2_rn(w11));
            g_wts[base] = wq;
        }
    } else {
        // ---------------- weight prep ----------------
        int i = (blk - PREP_NHWC_BLKS - PREP_OFF_BLKS) * 256 + tid;
        if (i < C_ * 32 * K2_) {
            int k = i % K2_;
            int t = i / K2_;
            int p = t % 32;
            int o = t / 32;
            float v0 = weight[((size_t)o * C_ + 2 * p)     * K2_ + k];
            float v1 = weight[((size_t)o * C_ + 2 * p + 1) * K2_ + k];
            __half2 h2 = __floats2half2_rn(v0, v1);
            g_wb[((size_t)k * C_ + o) * 36 + p] = h2u(h2);
        }
    }
}

// ---------------- Stage 2: fp16 NHWC gather fill + mma.sync fp16 ----------------
// block = half a (b,y) row (64 px), 4 warps; warp w owns px strip [16w,16w+16).
// grid 1024, 5 CTAs/SM. Per tap: HFMA2 bilinear fill -> barrier ->
// copy B(k+1) -> syncwarp -> GEMM (4 A LDSM4, 16 B LDSM4, 32 mma).
// smem u32: sA 64*36=2304  B0 2304  B1 2304  sDw uint4[576]=2304  sDi 576
#define SMU_A   0
#define SMU_B0  2304
#define SMU_B1  4608
#define SMU_DW  6912
#define SMU_DI  9216
#define SMU_TOT 9792     // * 4 = 39168 bytes

__global__ __launch_bounds__(128, 5) void deform_kernel(
    const float* __restrict__ bias,  // [64]
    float* __restrict__ out)         // [B,64,H,W]
{
    extern __shared__ uint32_t usm[];
    uint32_t* sA = usm + SMU_A;
    const uint4* sDw = (const uint4*)(usm + SMU_DW);
    const int*   sDi = (const int*)(usm + SMU_DI);

    const int tid  = threadIdx.x;
    const int wid  = tid >> 5;
    const int lid  = tid & 31;
    const int half = blockIdx.x & 1;
    const int y    = (blockIdx.x >> 1) & (H_ - 1);
    const int b    = blockIdx.x >> 8;

    const int pxw = wid * 16;         // local strip base (0..48)
    const int g   = lid >> 2;
    const int tg  = lid & 3;
    const int c4  = lid & 15;

    const uint32_t smb = smem_u32(usm);
    const int t8 = lid >> 3, r8 = lid & 7;
    // A: tiles (rows0-7,k0-7),(rows8-15,k0-7),(rows0-7,k8-15),(rows8-15,k8-15)
    const uint32_t aOff = smb + 4u * ((uint32_t)(pxw + (t8 & 1) * 8 + r8) * 36u
                                      + (uint32_t)(t8 >> 1) * 4u);
    // B: tiles (nt,k0),(nt,k1),(nt+1,k0),(nt+1,k1)
    const uint32_t bRow = 4u * ((uint32_t)((t8 >> 1) * 8 + r8) * 36u
                                + (uint32_t)(t8 & 1) * 4u);
    const uint32_t bBase0 = smb + 4u * SMU_B0;
    const uint32_t bBase1 = smb + 4u * SMU_B1;

    float4 acc[8];
#pragma unroll
    for (int nt = 0; nt < 8; nt++) acc[nt] = make_float4(0.f, 0.f, 0.f, 0.f);

    const __half* xtb = g_xth + (size_t)b * HW_ * C_;

    // ---- prologue: stage descriptors (9 taps x 64 px) + copy B(0) ----
    {
        const int rowbase = (b * K2_ * H_ + y) * W_ + half * 64;
        uint4* dDw = (uint4*)(usm + SMU_DW);
        int*   dDi = (int*)(usm + SMU_DI);
#pragma unroll
        for (int it = 0; it < 5; it++) {
            int i = tid + it * 128;            // over 576 = 9*64
            if (i < K2_ * 64) {
                int k  = i >> 6;
                int xx = i & 63;
                int src = rowbase + k * HW_ + xx;
                dDw[i] = __ldg(&g_wts[src]);
                dDi[i] = __ldg(&g_idx[src]);
            }
        }
        const float4* srcB = (const float4*)g_wb;
        float4* dstB = (float4*)(usm + SMU_B0);
#pragma unroll
        for (int it = 0; it < 5; it++) {
            int i = tid + it * 128;            // over 576 float4
            if (i < 576) dstB[i] = __ldg(srcB + i);
        }
    }
    __syncthreads();   // desc + B(0) visible

#pragma unroll 1
    for (int k = 0; k < K2_; k++) {
        // ---- warp-private bilinear fill of sA rows [pxw, pxw+16) ----
        {
#pragma unroll
            for (int j = 0; j < 8; j++) {
                const int pxl = pxw + 2 * j + (lid >> 4);   // local 0..63
                const int idx = k * 64 + pxl;
                const uint4 wq = sDw[idx];
                const int   di = sDi[idx];
                const int y0c = (di >> 24) & 255, y1c = (di >> 16) & 255;
                const int x0c = (di >> 8) & 255,  x1c = di & 255;
                const uint2 c00 = __ldg((const uint2*)(xtb + (size_t)(y0c * W_ + x0c) * C_) + c4);
                const uint2 c01 = __ldg((const uint2*)(xtb + (size_t)(y0c * W_ + x1c) * C_) + c4);
                const uint2 c10 = __ldg((const uint2*)(xtb + (size_t)(y1c * W_ + x0c) * C_) + c4);
                const uint2 c11 = __ldg((const uint2*)(xtb + (size_t)(y1c * W_ + x1c) * C_) + c4);
                __half2 s01 = __hmul2(u2h(c00.x), u2h(wq.x));
                s01 = __hfma2(u2h(c01.x), u2h(wq.y), s01);
                s01 = __hfma2(u2h(c10.x), u2h(wq.z), s01);
                s01 = __hfma2(u2h(c11.x), u2h(wq.w), s01);
                __half2 s23 = __hmul2(u2h(c00.y), u2h(wq.x));
                s23 = __hfma2(u2h(c01.y), u2h(wq.y), s23);
                s23 = __hfma2(u2h(c10.y), u2h(wq.z), s23);
                s23 = __hfma2(u2h(c11.y), u2h(wq.w), s23);
                *(uint2*)&sA[pxl * 36 + 2 * c4] = make_uint2(h2u(s01), h2u(s23));
            }
        }

        // barrier: (a) B(k) copy complete, (b) all GEMM(k-1) done before we
        // overwrite buf[(k+1)&1] below
        __syncthreads();

        // ---- cooperative copy of B(k+1) into alternate buffer ----
        if (k + 1 < K2_) {
            const float4* src = (const float4*)(g_wb + (size_t)(k + 1) * 2304);
            float4* dst = (float4*)(usm + (((k + 1) & 1) ? SMU_B1 : SMU_B0));
#pragma unroll
            for (int it = 0; it < 5; it++) {
                int i = tid + it * 128;
                if (i < 576) dst[i] = __ldg(src + i);
            }
        }

        __syncwarp();   // sA fill (cross-lane) visible to ldmatrix

        // ---- GEMM: 4 kt x (1 A LDSM4 + 4 B LDSM4 + 8 mma) ----
        const uint32_t bB = (k & 1) ? bBase1 : bBase0;
#pragma unroll
        for (int kt = 0; kt < 4; kt++) {
            uint32_t a0, a1, a2, a3;
            LDSM4(a0, a1, a2, a3, aOff + kt * 32u);
#pragma unroll
            for (int np = 0; np < 4; np++) {
                uint32_t b0, b1, b2, b3;
                LDSM4(b0, b1, b2, b3, bB + bRow + (uint32_t)np * 2304u + kt * 32u);
                mma_f16(acc[2 * np],     a0, a1, a2, a3, b0, b1);
                mma_f16(acc[2 * np + 1], a0, a1, a2, a3, b2, b3);
            }
        }
    }

    // ---- epilogue ----
    const int px0 = half * 64 + pxw + g;
#pragma unroll
    for (int nt = 0; nt < 8; nt++) {
        const int o = nt * 8 + 2 * tg;
        const float b0 = __ldg(&bias[o]);
        const float b1 = __ldg(&bias[o + 1]);
        float* r0 = out + (((size_t)b * C_ + o)     * H_ + y) * W_;
        float* r1 = out + (((size_t)b * C_ + o + 1) * H_ + y) * W_;
        r0[px0]     = acc[nt].x + b0;
        r1[px0]     = acc[nt].y + b1;
        r0[px0 + 8] = acc[nt].z + b0;
        r1[px0 + 8] = acc[nt].w + b1;
    }
}

// ---------------- launch ----------------
extern "C" void kernel_launch(void* const* d_in, const int* in_sizes, int n_in,
                              void* d_out, int out_size) {
    const float* x           = (const float*)d_in[0];
    const float* offset_feat = (const float*)d_in[1];
    const float* w_off       = (const float*)d_in[2];
    const float* b_off       = (const float*)d_in[3];
    const float* weight      = (const float*)d_in[4];
    const float* bias        = (const float*)d_in[5];
    float* out = (float*)d_out;

    static bool attr_set = false;
    if (!attr_set) {
        cudaFuncSetAttribute(deform_kernel,
                             cudaFuncAttributeMaxDynamicSharedMemorySize,
                             SMU_TOT * 4);
        attr_set = true;
    }

    prep_kernel<<<PREP_TOTAL, 256>>>(x, offset_feat, w_off, b_off, weight);
    deform_kernel<<<B_ * H_ * 2, 128, SMU_TOT * 4>>>(bias, out);
}

// round 14
// speedup vs baseline: 1.0955x; 1.0955x over previous
#include <cuda_runtime.h>
#include <cuda_fp16.h>
#include <math.h>
#include <cstdint>

typedef unsigned long long ull;

// Problem constants
#define B_    4
#define C_    64
#define H_    128
#define W_    128
#define HW_   (H_*W_)
#define OFFC_ 32
#define K2_   9
#define OCOFF 27

// ---------------- scratch ----------------
__device__ int    g_idx[B_ * K2_ * HW_];   // packed clamped corners
__device__ uint4  g_wts[B_ * K2_ * HW_];   // bilinear weights as dup'd half2 x4
__device__ __half g_xth[B_ * HW_ * C_];    // x in NHWC fp16: [b][y][x][c]
// W^T as f16x2 pairs (single fp16): [k][o][36 stride, 32 pairs used]
__device__ uint32_t g_wb[K2_ * C_ * 36];

// ---------------- helpers ----------------
__device__ __forceinline__ uint32_t smem_u32(const void* p) {
    uint32_t a;
    asm("{ .reg .u64 t; cvta.to.shared.u64 t, %1; cvt.u32.u64 %0, t; }" : "=r"(a) : "l"(p));
    return a;
}
__device__ __forceinline__ void ffma2(ull& d, ull a, ull b) {
    asm("fma.rn.f32x2 %0, %1, %2, %0;" : "+l"(d) : "l"(a), "l"(b));
}
__device__ __forceinline__ ull dup2(float s) {
    ull d;
    asm("mov.b64 %0, {%1, %1};" : "=l"(d) : "f"(s));
    return d;
}
__device__ __forceinline__ void mma_f16(float4& d,
                                        uint32_t a0, uint32_t a1, uint32_t a2, uint32_t a3,
                                        uint32_t b0, uint32_t b1) {
    asm volatile(
        "mma.sync.aligned.m16n8k16.row.col.f32.f16.f16.f32 "
        "{%0,%1,%2,%3}, {%4,%5,%6,%7}, {%8,%9}, {%0,%1,%2,%3};"
        : "+f"(d.x), "+f"(d.y), "+f"(d.z), "+f"(d.w)
        : "r"(a0), "r"(a1), "r"(a2), "r"(a3), "r"(b0), "r"(b1));
}
#define LDSM4(r0, r1, r2, r3, addr)                                           \
    asm volatile("ldmatrix.sync.aligned.m8n8.x4.shared.b16 {%0,%1,%2,%3}, [%4];" \
                 : "=r"(r0), "=r"(r1), "=r"(r2), "=r"(r3) : "r"(addr))
__device__ __forceinline__ __half2 u2h(uint32_t u) {
    return *reinterpret_cast<__half2*>(&u);
}
__device__ __forceinline__ uint32_t h2u(__half2 h) {
    return *reinterpret_cast<uint32_t*>(&h);
}

// ---------------- Fused prep kernel (128 threads, per-role geometry preserved) ----
// blocks [0,512)      : offset conv + descriptors, ONE (b,y) row each (as R11)
// blocks [512,1024)   : x NCHW -> NHWC fp16, one (b,y) row each
// blocks [1024,1168)  : weight -> fp16 pairs, 144 blocks x 128 = 18432 elems
#define PREP_OFF_BLKS  512
#define PREP_NHWC_BLKS 512
#define PREP_W_BLKS    144
#define PREP_TOTAL     (PREP_OFF_BLKS + PREP_NHWC_BLKS + PREP_W_BLKS)

__global__ __launch_bounds__(128) void prep_kernel(
    const float* __restrict__ x,             // [B,64,H,W]
    const float* __restrict__ offset_feat,   // [B,32,H,W]
    const float* __restrict__ w_off,         // [27,32,3,3]
    const float* __restrict__ b_off,         // [27]
    const float* __restrict__ weight)        // [64,64,3,3]
{
    __shared__ __align__(16) char sraw[33024];
    __shared__ __align__(16) float s_boff[28];

    const int blk = blockIdx.x;
    const int tid = threadIdx.x;

    if (blk < PREP_OFF_BLKS) {
        // ---------------- offset conv + descriptors (one row, as R11) ----------------
        float* s_w = (float*)sraw;                // [288][28]
        const int y = blk & (H_ - 1);
        const int b = blk >> 7;
        const int xx = tid;

        for (int i = tid; i < OCOFF * 288; i += 128) {
            int oc = i / 288;
            int r  = i % 288;
            s_w[r * 28 + oc] = w_off[i];
        }
        if (tid < 28) s_boff[tid] = (tid < OCOFF) ? b_off[tid] : 0.f;
        __syncthreads();

        ull acc2[14];
#pragma unroll
        for (int j = 0; j < 14; j++) acc2[j] = ((const ull*)s_boff)[j];

        const float* fbase = offset_feat + (size_t)b * OFFC_ * HW_;

#pragma unroll
        for (int ky = 0; ky < 3; ky++) {
            const int iy = y - 1 + ky;
            const bool vy = ((unsigned)iy < (unsigned)H_);
#pragma unroll
            for (int kx = 0; kx < 3; kx++) {
                const int ix = xx - 1 + kx;
                const bool v = vy && ((unsigned)ix < (unsigned)W_);
                const int tap = ky * 3 + kx;
                const float* ip = fbase + iy * W_ + ix;
#pragma unroll 4
                for (int c = 0; c < OFFC_; c++) {
                    float vv = v ? __ldg(ip + c * HW_) : 0.f;
                    ull v2 = dup2(vv);
                    const ulonglong2* wp = (const ulonglong2*)(s_w + (c * 9 + tap) * 28);
#pragma unroll
                    for (int j = 0; j < 7; j++) {
                        ulonglong2 ww = wp[j];
                        ffma2(acc2[2 * j],     ww.x, v2);
                        ffma2(acc2[2 * j + 1], ww.y, v2);
                    }
                }
            }
        }

        float acc[28];
#pragma unroll
        for (int j = 0; j < 14; j++) {
            asm("mov.b64 {%0, %1}, %2;" : "=f"(acc[2 * j]), "=f"(acc[2 * j + 1]) : "l"(acc2[j]));
        }

#pragma unroll
        for (int k = 0; k < K2_; k++) {
            float dy = acc[2 * k];
            float dx = acc[2 * k + 1];
            float m  = 1.f / (1.f + __expf(-acc[18 + k]));

            float py = (float)(y - 1 + (k / 3)) + dy;
            float px = (float)(xx - 1 + (k % 3)) + dx;
            float y0f = floorf(py), x0f = floorf(px);
            float wy1 = py - y0f,   wx1 = px - x0f;
            float wy0 = 1.f - wy1,  wx0 = 1.f - wx1;
            int y0 = (int)y0f, x0 = (int)x0f;
            int y1 = y0 + 1,   x1 = x0 + 1;

            bool vy0 = ((unsigned)y0 < (unsigned)H_);
            bool vy1 = ((unsigned)y1 < (unsigned)H_);
            bool vx0 = ((unsigned)x0 < (unsigned)W_);
            bool vx1 = ((unsigned)x1 < (unsigned)W_);

            float w00 = wy0 * wx0 * m * (float)(vy0 && vx0);
            float w01 = wy0 * wx1 * m * (float)(vy0 && vx1);
            float w10 = wy1 * wx0 * m * (float)(vy1 && vx0);
            float w11 = wy1 * wx1 * m * (float)(vy1 && vx1);

            int y0c = min(max(y0, 0), H_ - 1);
            int y1c = min(max(y1, 0), H_ - 1);
            int x0c = min(max(x0, 0), W_ - 1);
            int x1c = min(max(x1, 0), W_ - 1);

            int base = ((b * K2_ + k) * H_ + y) * W_ + xx;
            g_idx[base] = (y0c << 24) | (y1c << 16) | (x0c << 8) | x1c;
            uint4 wq;
            wq.x = h2u(__float2half2_rn(w00));
            wq.y = h2u(__float2half2_rn(w01));
            wq.z = h2u(__float2half2_rn(w10));
            wq.w = h2u(__float2half2_rn(w11));
            g_wts[base] = wq;
        }
    } else if (blk < PREP_OFF_BLKS + PREP_NHWC_BLKS) {
        // ---------------- NHWC transpose (one row, 128 threads) ----------------
        float* st = (float*)sraw;                 // [64][129]
        const int r  = blk - PREP_OFF_BLKS;
        const int y  = r & (H_ - 1);
        const int b  = r >> 7;

        const float* src = x + ((size_t)b * C_ * H_ + y) * W_;
#pragma unroll
        for (int i = 0; i < 16; i++) {
            int idx = tid + i * 128;          // over 2048 float4
            int c   = idx >> 5;
            int x4  = idx & 31;
            float4 v = __ldg((const float4*)(src + (size_t)c * HW_) + x4);
            float* d = st + c * 129 + x4 * 4;
            d[0] = v.x; d[1] = v.y; d[2] = v.z; d[3] = v.w;
        }
        __syncthreads();

        __half* dst = g_xth + ((size_t)(b * H_ + y) * W_) * C_;
#pragma unroll
        for (int i = 0; i < 16; i++) {
            int idx = tid + i * 128;          // over 2048 uint2
            int px  = idx >> 4;
            int cq  = idx & 15;
            float v0 = st[(cq * 4 + 0) * 129 + px];
            float v1 = st[(cq * 4 + 1) * 129 + px];
            float v2 = st[(cq * 4 + 2) * 129 + px];
            float v3 = st[(cq * 4 + 3) * 129 + px];
            uint2 o2;
            o2.x = h2u(__floats2half2_rn(v0, v1));
            o2.y = h2u(__floats2half2_rn(v2, v3));
            *(uint2*)(dst + (size_t)px * C_ + cq * 4) = o2;
        }
    } else {
        // ---------------- weight prep ----------------
        int i = (blk - PREP_OFF_BLKS - PREP_NHWC_BLKS) * 128 + tid;
        if (i < C_ * 32 * K2_) {
            int k = i % K2_;
            int t = i / K2_;
            int p = t % 32;
            int o = t / 32;
            float v0 = weight[((size_t)o * C_ + 2 * p)     * K2_ + k];
            float v1 = weight[((size_t)o * C_ + 2 * p + 1) * K2_ + k];
            __half2 h2 = __floats2half2_rn(v0, v1);
            g_wb[((size_t)k * C_ + o) * 36 + p] = h2u(h2);
        }
    }
}

// ---------------- Stage 2: fp16 NHWC gather fill + mma.sync fp16 (R11 exact) ----
// block = half a (b,y) row (64 px), 4 warps; warp w owns px strip [16w,16w+16).
// grid 1024, 4 CTAs/SM. Per tap: HFMA2 bilinear fill -> barrier ->
// copy B(k+1) -> syncwarp -> GEMM (4 A LDSM4, 16 B LDSM4, 32 mma).
// smem u32: sA 64*36=2304  B0 2304  B1 2304  sDw uint4[576]=2304  sDi 576
#define SMU_A   0
#define SMU_B0  2304
#define SMU_B1  4608
#define SMU_DW  6912
#define SMU_DI  9216
#define SMU_TOT 9792     // * 4 = 39168 bytes

__global__ __launch_bounds__(128, 4) void deform_kernel(
    const float* __restrict__ bias,  // [64]
    float* __restrict__ out)         // [B,64,H,W]
{
    extern __shared__ uint32_t usm[];
    uint32_t* sA = usm + SMU_A;
    const uint4* sDw = (const uint4*)(usm + SMU_DW);
    const int*   sDi = (const int*)(usm + SMU_DI);

    const int tid  = threadIdx.x;
    const int wid  = tid >> 5;
    const int lid  = tid & 31;
    const int half = blockIdx.x & 1;
    const int y    = (blockIdx.x >> 1) & (H_ - 1);
    const int b    = blockIdx.x >> 8;

    const int pxw = wid * 16;         // local strip base (0..48)
    const int g   = lid >> 2;
    const int tg  = lid & 3;
    const int c4  = lid & 15;

    const uint32_t smb = smem_u32(usm);
    const int t8 = lid >> 3, r8 = lid & 7;
    // A: tiles (rows0-7,k0-7),(rows8-15,k0-7),(rows0-7,k8-15),(rows8-15,k8-15)
    const uint32_t aOff = smb + 4u * ((uint32_t)(pxw + (t8 & 1) * 8 + r8) * 36u
                                      + (uint32_t)(t8 >> 1) * 4u);
    // B: tiles (nt,k0),(nt,k1),(nt+1,k0),(nt+1,k1)
    const uint32_t bRow = 4u * ((uint32_t)((t8 >> 1) * 8 + r8) * 36u
                                + (uint32_t)(t8 & 1) * 4u);
    const uint32_t bBase0 = smb + 4u * SMU_B0;
    const uint32_t bBase1 = smb + 4u * SMU_B1;

    float4 acc[8];
#pragma unroll
    for (int nt = 0; nt < 8; nt++) acc[nt] = make_float4(0.f, 0.f, 0.f, 0.f);

    const __half* xtb = g_xth + (size_t)b * HW_ * C_;

    // ---- prologue: stage descriptors (9 taps x 64 px) + copy B(0) ----
    {
        const int rowbase = (b * K2_ * H_ + y) * W_ + half * 64;
        uint4* dDw = (uint4*)(usm + SMU_DW);
        int*   dDi = (int*)(usm + SMU_DI);
#pragma unroll
        for (int it = 0; it < 5; it++) {
            int i = tid + it * 128;            // over 576 = 9*64
            if (i < K2_ * 64) {
                int k  = i >> 6;
                int xx = i & 63;
                int src = rowbase + k * HW_ + xx;
                dDw[i] = __ldg(&g_wts[src]);
                dDi[i] = __ldg(&g_idx[src]);
            }
        }
        const float4* srcB = (const float4*)g_wb;
        float4* dstB = (float4*)(usm + SMU_B0);
#pragma unroll
        for (int it = 0; it < 5; it++) {
            int i = tid + it * 128;            // over 576 float4
            if (i < 576) dstB[i] = __ldg(srcB + i);
        }
    }
    __syncthreads();   // desc + B(0) visible

#pragma unroll 1
    for (int k = 0; k < K2_; k++) {
        // ---- warp-private bilinear fill of sA rows [pxw, pxw+16) ----
        {
#pragma unroll
            for (int j = 0; j < 8; j++) {
                const int pxl = pxw + 2 * j + (lid >> 4);   // local 0..63
                const int idx = k * 64 + pxl;
                const uint4 wq = sDw[idx];
                const int   di = sDi[idx];
                const int y0c = (di >> 24) & 255, y1c = (di >> 16) & 255;
                const int x0c = (di >> 8) & 255,  x1c = di & 255;
                const uint2 c00 = __ldg((const uint2*)(xtb + (size_t)(y0c * W_ + x0c) * C_) + c4);
                const uint2 c01 = __ldg((const uint2*)(xtb + (size_t)(y0c * W_ + x1c) * C_) + c4);
                const uint2 c10 = __ldg((const uint2*)(xtb + (size_t)(y1c * W_ + x0c) * C_) + c4);
                const uint2 c11 = __ldg((const uint2*)(xtb + (size_t)(y1c * W_ + x1c) * C_) + c4);
                __half2 s01 = __hmul2(u2h(c00.x), u2h(wq.x));
                s01 = __hfma2(u2h(c01.x), u2h(wq.y), s01);
                s01 = __hfma2(u2h(c10.x), u2h(wq.z), s01);
                s01 = __hfma2(u2h(c11.x), u2h(wq.w), s01);
                __half2 s23 = __hmul2(u2h(c00.y), u2h(wq.x));
                s23 = __hfma2(u2h(c01.y), u2h(wq.y), s23);
                s23 = __hfma2(u2h(c10.y), u2h(wq.z), s23);
                s23 = __hfma2(u2h(c11.y), u2h(wq.w), s23);
                *(uint2*)&sA[pxl * 36 + 2 * c4] = make_uint2(h2u(s01), h2u(s23));
            }
        }

        // barrier: (a) B(k) copy complete, (b) all GEMM(k-1) done before we
        // overwrite buf[(k+1)&1] below
        __syncthreads();

        // ---- cooperative copy of B(k+1) into alternate buffer ----
        if (k + 1 < K2_) {
            const float4* src = (const float4*)(g_wb + (size_t)(k + 1) * 2304);
            float4* dst = (float4*)(usm + (((k + 1) & 1) ? SMU_B1 : SMU_B0));
#pragma unroll
            for (int it = 0; it < 5; it++) {
                int i = tid + it * 128;
                if (i < 576) dst[i] = __ldg(src + i);
            }
        }

        __syncwarp();   // sA fill (cross-lane) visible to ldmatrix

        // ---- GEMM: 4 kt x (1 A LDSM4 + 4 B LDSM4 + 8 mma) ----
        const uint32_t bB = (k & 1) ? bBase1 : bBase0;
#pragma unroll
        for (int kt = 0; kt < 4; kt++) {
            uint32_t a0, a1, a2, a3;
            LDSM4(a0, a1, a2, a3, aOff + kt * 32u);
#pragma unroll
            for (int np = 0; np < 4; np++) {
                uint32_t b0, b1, b2, b3;
                LDSM4(b0, b1, b2, b3, bB + bRow + (uint32_t)np * 2304u + kt * 32u);
                mma_f16(acc[2 * np],     a0, a1, a2, a3, b0, b1);
                mma_f16(acc[2 * np + 1], a0, a1, a2, a3, b2, b3);
            }
        }
    }

    // ---- epilogue ----
    const int px0 = half * 64 + pxw + g;
#pragma unroll
    for (int nt = 0; nt < 8; nt++) {
        const int o = nt * 8 + 2 * tg;
        const float b0 = __ldg(&bias[o]);
        const float b1 = __ldg(&bias[o + 1]);
        float* r0 = out + (((size_t)b * C_ + o)     * H_ + y) * W_;
        float* r1 = out + (((size_t)b * C_ + o + 1) * H_ + y) * W_;
        r0[px0]     = acc[nt].x + b0;
        r1[px0]     = acc[nt].y + b1;
        r0[px0 + 8] = acc[nt].z + b0;
        r1[px0 + 8] = acc[nt].w + b1;
    }
}

// ---------------- launch ----------------
extern "C" void kernel_launch(void* const* d_in, const int* in_sizes, int n_in,
                              void* d_out, int out_size) {
    const float* x           = (const float*)d_in[0];
    const float* offset_feat = (const float*)d_in[1];
    const float* w_off       = (const float*)d_in[2];
    const float* b_off       = (const float*)d_in[3];
    const float* weight      = (const float*)d_in[4];
    const float* bias        = (const float*)d_in[5];
    float* out = (float*)d_out;

    static bool attr_set = false;
    if (!attr_set) {
        cudaFuncSetAttribute(deform_kernel,
                             cudaFuncAttributeMaxDynamicSharedMemorySize,
                             SMU_TOT * 4);
        attr_set = true;
    }

    prep_kernel<<<PREP_TOTAL, 128>>>(x, offset_feat, w_off, b_off, weight);
    deform_kernel<<<B_ * H_ * 2, 128, SMU_TOT * 4>>>(bias, out);
}

// round 15
// speedup vs baseline: 1.1378x; 1.0386x over previous
#include <cuda_runtime.h>
#include <cuda_fp16.h>
#include <math.h>
#include <cstdint>

typedef unsigned long long ull;

// Problem constants
#define B_    4
#define C_    64
#define H_    128
#define W_    128
#define HW_   (H_*W_)
#define OFFC_ 32
#define K2_   9
#define OCOFF 27

// ---------------- scratch ----------------
__device__ int    g_idx[B_ * K2_ * HW_];   // packed clamped corners
__device__ uint4  g_wts[B_ * K2_ * HW_];   // bilinear weights as dup'd half2 x4
__device__ __half g_xth[B_ * HW_ * C_];    // x in NHWC fp16: [b][y][x][c]
// W^T as f16x2 pairs (single fp16): [k][o][36 stride, 32 pairs used]
__device__ uint32_t g_wb[K2_ * C_ * 36];

// ---------------- helpers ----------------
__device__ __forceinline__ uint32_t smem_u32(const void* p) {
    uint32_t a;
    asm("{ .reg .u64 t; cvta.to.shared.u64 t, %1; cvt.u32.u64 %0, t; }" : "=r"(a) : "l"(p));
    return a;
}
__device__ __forceinline__ void ffma2(ull& d, ull a, ull b) {
    asm("fma.rn.f32x2 %0, %1, %2, %0;" : "+l"(d) : "l"(a), "l"(b));
}
__device__ __forceinline__ ull dup2(float s) {
    ull d;
    asm("mov.b64 %0, {%1, %1};" : "=l"(d) : "f"(s));
    return d;
}
__device__ __forceinline__ void mma_f16(float4& d,
                                        uint32_t a0, uint32_t a1, uint32_t a2, uint32_t a3,
                                        uint32_t b0, uint32_t b1) {
    asm volatile(
        "mma.sync.aligned.m16n8k16.row.col.f32.f16.f16.f32 "
        "{%0,%1,%2,%3}, {%4,%5,%6,%7}, {%8,%9}, {%0,%1,%2,%3};"
        : "+f"(d.x), "+f"(d.y), "+f"(d.z), "+f"(d.w)
        : "r"(a0), "r"(a1), "r"(a2), "r"(a3), "r"(b0), "r"(b1));
}
#define LDSM4(r0, r1, r2, r3, addr)                                           \
    asm volatile("ldmatrix.sync.aligned.m8n8.x4.shared.b16 {%0,%1,%2,%3}, [%4];" \
                 : "=r"(r0), "=r"(r1), "=r"(r2), "=r"(r3) : "r"(addr))
__device__ __forceinline__ __half2 u2h(uint32_t u) {
    return *reinterpret_cast<__half2*>(&u);
}
__device__ __forceinline__ uint32_t h2u(__half2 h) {
    return *reinterpret_cast<uint32_t*>(&h);
}

// ---------------- Stage 0a: weight -> fp16 pairs, [k][o][pair] ----------------
__global__ void prep_w_kernel(const float* __restrict__ w) {
    int i = blockIdx.x * 256 + threadIdx.x;    // over 64o * 32p * 9k
    if (i >= C_ * 32 * K2_) return;
    int k = i % K2_;
    int t = i / K2_;
    int p = t % 32;
    int o = t / 32;
    float v0 = w[((size_t)o * C_ + 2 * p)     * K2_ + k];
    float v1 = w[((size_t)o * C_ + 2 * p + 1) * K2_ + k];
    __half2 h2 = __floats2half2_rn(v0, v1);
    g_wb[((size_t)k * C_ + o) * 36 + p] = h2u(h2);
}

// ---------------- Stage 0b: x NCHW -> NHWC fp16 ----------------
__global__ __launch_bounds__(256) void nhwc_kernel(const float* __restrict__ x) {
    __shared__ float st[C_ * 129];
    const int tid = threadIdx.x;
    const int y   = blockIdx.x & (H_ - 1);
    const int b   = blockIdx.x >> 7;

    const float* src = x + ((size_t)b * C_ * H_ + y) * W_;
#pragma unroll
    for (int i = 0; i < 8; i++) {
        int idx = tid + i * 256;
        int c   = idx >> 5;
        int x4  = idx & 31;
        float4 v = __ldg((const float4*)(src + (size_t)c * HW_) + x4);
        float* d = st + c * 129 + x4 * 4;
        d[0] = v.x; d[1] = v.y; d[2] = v.z; d[3] = v.w;
    }
    __syncthreads();

    __half* dst = g_xth + ((size_t)(b * H_ + y) * W_) * C_;
#pragma unroll
    for (int i = 0; i < 8; i++) {
        int idx = tid + i * 256;
        int px  = idx >> 4;
        int cq  = idx & 15;
        float v0 = st[(cq * 4 + 0) * 129 + px];
        float v1 = st[(cq * 4 + 1) * 129 + px];
        float v2 = st[(cq * 4 + 2) * 129 + px];
        float v3 = st[(cq * 4 + 3) * 129 + px];
        uint2 o2;
        o2.x = h2u(__floats2half2_rn(v0, v1));
        o2.y = h2u(__floats2half2_rn(v2, v3));
        *(uint2*)(dst + (size_t)px * C_ + cq * 4) = o2;
    }
}

// ---------------- Stage 1: offset conv + bilinear descriptor precompute ----------------
__global__ __launch_bounds__(128) void offset_kernel(
    const float* __restrict__ offset_feat,   // [B,32,H,W]
    const float* __restrict__ w_off,         // [27,32,3,3]
    const float* __restrict__ b_off)         // [27]
{
    __shared__ __align__(16) float s_w[288 * 28];
    __shared__ __align__(16) float s_boff[28];

    const int tid = threadIdx.x;
    const int y   = blockIdx.x & (H_ - 1);
    const int b   = blockIdx.x >> 7;
    const int x   = tid;

    for (int i = tid; i < OCOFF * 288; i += 128) {
        int oc = i / 288;
        int r  = i % 288;
        s_w[r * 28 + oc] = w_off[i];
    }
    if (tid < 28) s_boff[tid] = (tid < OCOFF) ? b_off[tid] : 0.f;
    __syncthreads();

    ull acc2[14];
#pragma unroll
    for (int j = 0; j < 14; j++) acc2[j] = ((const ull*)s_boff)[j];

    const float* fbase = offset_feat + (size_t)b * OFFC_ * HW_;

#pragma unroll
    for (int ky = 0; ky < 3; ky++) {
        const int iy = y - 1 + ky;
        const bool vy = ((unsigned)iy < (unsigned)H_);
#pragma unroll
        for (int kx = 0; kx < 3; kx++) {
            const int ix = x - 1 + kx;
            const bool v = vy && ((unsigned)ix < (unsigned)W_);
            const int tap = ky * 3 + kx;
            const float* ip = fbase + iy * W_ + ix;
#pragma unroll 4
            for (int c = 0; c < OFFC_; c++) {
                float vv = v ? __ldg(ip + c * HW_) : 0.f;
                ull v2 = dup2(vv);
                const ulonglong2* wp = (const ulonglong2*)(s_w + (c * 9 + tap) * 28);
#pragma unroll
                for (int j = 0; j < 7; j++) {
                    ulonglong2 ww = wp[j];
                    ffma2(acc2[2 * j],     ww.x, v2);
                    ffma2(acc2[2 * j + 1], ww.y, v2);
                }
            }
        }
    }

    float acc[28];
#pragma unroll
    for (int j = 0; j < 14; j++) {
        asm("mov.b64 {%0, %1}, %2;" : "=f"(acc[2 * j]), "=f"(acc[2 * j + 1]) : "l"(acc2[j]));
    }

#pragma unroll
    for (int k = 0; k < K2_; k++) {
        float dy = acc[2 * k];
        float dx = acc[2 * k + 1];
        float m  = 1.f / (1.f + __expf(-acc[18 + k]));

        float py = (float)(y - 1 + (k / 3)) + dy;
        float px = (float)(x - 1 + (k % 3)) + dx;
        float y0f = floorf(py), x0f = floorf(px);
        float wy1 = py - y0f,   wx1 = px - x0f;
        float wy0 = 1.f - wy1,  wx0 = 1.f - wx1;
        int y0 = (int)y0f, x0 = (int)x0f;
        int y1 = y0 + 1,   x1 = x0 + 1;

        bool vy0 = ((unsigned)y0 < (unsigned)H_);
        bool vy1 = ((unsigned)y1 < (unsigned)H_);
        bool vx0 = ((unsigned)x0 < (unsigned)W_);
        bool vx1 = ((unsigned)x1 < (unsigned)W_);

        float w00 = wy0 * wx0 * m * (float)(vy0 && vx0);
        float w01 = wy0 * wx1 * m * (float)(vy0 && vx1);
        float w10 = wy1 * wx0 * m * (float)(vy1 && vx0);
        float w11 = wy1 * wx1 * m * (float)(vy1 && vx1);

        int y0c = min(max(y0, 0), H_ - 1);
        int y1c = min(max(y1, 0), H_ - 1);
        int x0c = min(max(x0, 0), W_ - 1);
        int x1c = min(max(x1, 0), W_ - 1);

        int base = ((b * K2_ + k) * H_ + y) * W_ + x;
        g_idx[base] = (y0c << 24) | (y1c << 16) | (x0c << 8) | x1c;
        uint4 wq;
        wq.x = h2u(__float2half2_rn(w00));
        wq.y = h2u(__float2half2_rn(w01));
        wq.z = h2u(__float2half2_rn(w10));
        wq.w = h2u(__float2half2_rn(w11));
        g_wts[base] = wq;
    }
}

// ---------------- Stage 2: double-buffered A pipeline + mma.sync fp16 ----------------
// block = half a (b,y) row (64 px), 4 warps; warp w owns px strip [16w,16w+16).
// grid 1024, 4 CTAs/SM. Pipeline per iter k:
//   barrier; [copyB(k+1); fill(k+1)->A[(k+1)&1]]; GEMM(k) from A[k&1],B[k&1]
// -> each warp's fill LDGs drain under its own mma stream.
// smem u32: A0 2304  A1 2304  B0 2304  B1 2304  sDw uint4[576]=2304  sDi 576
#define SMU_A0  0
#define SMU_A1  2304
#define SMU_B0  4608
#define SMU_B1  6912
#define SMU_DW  9216
#define SMU_DI  11520
#define SMU_TOT 12096     // * 4 = 48384 bytes

__global__ __launch_bounds__(128, 4) void deform_kernel(
    const float* __restrict__ bias,  // [64]
    float* __restrict__ out)         // [B,64,H,W]
{
    extern __shared__ uint32_t usm[];
    const uint4* sDw = (const uint4*)(usm + SMU_DW);
    const int*   sDi = (const int*)(usm + SMU_DI);

    const int tid  = threadIdx.x;
    const int wid  = tid >> 5;
    const int lid  = tid & 31;
    const int half = blockIdx.x & 1;
    const int y    = (blockIdx.x >> 1) & (H_ - 1);
    const int b    = blockIdx.x >> 8;

    const int pxw = wid * 16;         // local strip base (0..48)
    const int g   = lid >> 2;
    const int tg  = lid & 3;
    const int c4  = lid & 15;

    const uint32_t smb = smem_u32(usm);
    const int t8 = lid >> 3, r8 = lid & 7;
    // A fragment base (row part); add buffer base at use
    const uint32_t aRow = 4u * ((uint32_t)(pxw + (t8 & 1) * 8 + r8) * 36u
                                + (uint32_t)(t8 >> 1) * 4u);
    const uint32_t aBase0 = smb + 4u * SMU_A0 + aRow;
    const uint32_t aBase1 = smb + 4u * SMU_A1 + aRow;
    // B: tiles (nt,k0),(nt,k1),(nt+1,k0),(nt+1,k1)
    const uint32_t bRow = 4u * ((uint32_t)((t8 >> 1) * 8 + r8) * 36u
                                + (uint32_t)(t8 & 1) * 4u);
    const uint32_t bBase0 = smb + 4u * SMU_B0 + bRow;
    const uint32_t bBase1 = smb + 4u * SMU_B1 + bRow;

    float4 acc[8];
#pragma unroll
    for (int nt = 0; nt < 8; nt++) acc[nt] = make_float4(0.f, 0.f, 0.f, 0.f);

    const __half* xtb = g_xth + (size_t)b * HW_ * C_;

    // ---- prologue: stage descriptors (9 taps x 64 px) + copy B(0) ----
    {
        const int rowbase = (b * K2_ * H_ + y) * W_ + half * 64;
        uint4* dDw = (uint4*)(usm + SMU_DW);
        int*   dDi = (int*)(usm + SMU_DI);
#pragma unroll
        for (int it = 0; it < 5; it++) {
            int i = tid + it * 128;            // over 576 = 9*64
            if (i < K2_ * 64) {
                int k  = i >> 6;
                int xx = i & 63;
                int src = rowbase + k * HW_ + xx;
                dDw[i] = __ldg(&g_wts[src]);
                dDi[i] = __ldg(&g_idx[src]);
            }
        }
        const float4* srcB = (const float4*)g_wb;
        float4* dstB = (float4*)(usm + SMU_B0);
#pragma unroll
        for (int it = 0; it < 5; it++) {
            int i = tid + it * 128;            // over 576 float4
            if (i < 576) dstB[i] = __ldg(srcB + i);
        }
    }
    __syncthreads();   // desc + B(0) visible

    // ---- fill(0) into A0 ----
#pragma unroll
    for (int j = 0; j < 8; j++) {
        const int pxl = pxw + 2 * j + (lid >> 4);
        const uint4 wq = sDw[pxl];
        const int   di = sDi[pxl];
        const int y0c = (di >> 24) & 255, y1c = (di >> 16) & 255;
        const int x0c = (di >> 8) & 255,  x1c = di & 255;
        const uint2 c00 = __ldg((const uint2*)(xtb + (size_t)(y0c * W_ + x0c) * C_) + c4);
        const uint2 c01 = __ldg((const uint2*)(xtb + (size_t)(y0c * W_ + x1c) * C_) + c4);
        const uint2 c10 = __ldg((const uint2*)(xtb + (size_t)(y1c * W_ + x0c) * C_) + c4);
        const uint2 c11 = __ldg((const uint2*)(xtb + (size_t)(y1c * W_ + x1c) * C_) + c4);
        __half2 s01 = __hmul2(u2h(c00.x), u2h(wq.x));
        s01 = __hfma2(u2h(c01.x), u2h(wq.y), s01);
        s01 = __hfma2(u2h(c10.x), u2h(wq.z), s01);
        s01 = __hfma2(u2h(c11.x), u2h(wq.w), s01);
        __half2 s23 = __hmul2(u2h(c00.y), u2h(wq.x));
        s23 = __hfma2(u2h(c01.y), u2h(wq.y), s23);
        s23 = __hfma2(u2h(c10.y), u2h(wq.z), s23);
        s23 = __hfma2(u2h(c11.y), u2h(wq.w), s23);
        *(uint2*)&usm[SMU_A0 + pxl * 36 + 2 * c4] = make_uint2(h2u(s01), h2u(s23));
    }

#pragma unroll 1
    for (int k = 0; k < K2_; k++) {
        // barrier: fill(k) visible to all; GEMM(k-1) done -> A/B[(k+1)&1] reusable
        __syncthreads();

        if (k + 1 < K2_) {
            // ---- cooperative copy of B(k+1) ----
            const float4* src = (const float4*)(g_wb + (size_t)(k + 1) * 2304);
            float4* dst = (float4*)(usm + (((k + 1) & 1) ? SMU_B1 : SMU_B0));
#pragma unroll
            for (int it = 0; it < 5; it++) {
                int i = tid + it * 128;
                if (i < 576) dst[i] = __ldg(src + i);
            }

            // ---- fill(k+1) into A[(k+1)&1] (LDGs drain under GEMM(k) below) ----
            uint32_t* sAn = usm + (((k + 1) & 1) ? SMU_A1 : SMU_A0);
#pragma unroll
            for (int j = 0; j < 8; j++) {
                const int pxl = pxw + 2 * j + (lid >> 4);
                const int idx = (k + 1) * 64 + pxl;
                const uint4 wq = sDw[idx];
                const int   di = sDi[idx];
                const int y0c = (di >> 24) & 255, y1c = (di >> 16) & 255;
                const int x0c = (di >> 8) & 255,  x1c = di & 255;
                const uint2 c00 = __ldg((const uint2*)(xtb + (size_t)(y0c * W_ + x0c) * C_) + c4);
                const uint2 c01 = __ldg((const uint2*)(xtb + (size_t)(y0c * W_ + x1c) * C_) + c4);
                const uint2 c10 = __ldg((const uint2*)(xtb + (size_t)(y1c * W_ + x0c) * C_) + c4);
                const uint2 c11 = __ldg((const uint2*)(xtb + (size_t)(y1c * W_ + x1c) * C_) + c4);
                __half2 s01 = __hmul2(u2h(c00.x), u2h(wq.x));
                s01 = __hfma2(u2h(c01.x), u2h(wq.y), s01);
                s01 = __hfma2(u2h(c10.x), u2h(wq.z), s01);
                s01 = __hfma2(u2h(c11.x), u2h(wq.w), s01);
                __half2 s23 = __hmul2(u2h(c00.y), u2h(wq.x));
                s23 = __hfma2(u2h(c01.y), u2h(wq.y), s23);
                s23 = __hfma2(u2h(c10.y), u2h(wq.z), s23);
                s23 = __hfma2(u2h(c11.y), u2h(wq.w), s23);
                *(uint2*)&sAn[pxl * 36 + 2 * c4] = make_uint2(h2u(s01), h2u(s23));
            }
        }

        // ---- GEMM(k): 4 kt x (1 A LDSM4 + 4 B LDSM4 + 8 mma) ----
        const uint32_t aB = (k & 1) ? aBase1 : aBase0;
        const uint32_t bB = (k & 1) ? bBase1 : bBase0;
#pragma unroll
        for (int kt = 0; kt < 4; kt++) {
            uint32_t a0, a1, a2, a3;
            LDSM4(a0, a1, a2, a3, aB + kt * 32u);
#pragma unroll
            for (int np = 0; np < 4; np++) {
                uint32_t b0, b1, b2, b3;
                LDSM4(b0, b1, b2, b3, bB + (uint32_t)np * 2304u + kt * 32u);
                mma_f16(acc[2 * np],     a0, a1, a2, a3, b0, b1);
                mma_f16(acc[2 * np + 1], a0, a1, a2, a3, b2, b3);
            }
        }
    }

    // ---- epilogue ----
    const int px0 = half * 64 + pxw + g;
#pragma unroll
    for (int nt = 0; nt < 8; nt++) {
        const int o = nt * 8 + 2 * tg;
        const float b0 = __ldg(&bias[o]);
        const float b1 = __ldg(&bias[o + 1]);
        float* r0 = out + (((size_t)b * C_ + o)     * H_ + y) * W_;
        float* r1 = out + (((size_t)b * C_ + o + 1) * H_ + y) * W_;
        r0[px0]     = acc[nt].x + b0;
        r1[px0]     = acc[nt].y + b1;
        r0[px0 + 8] = acc[nt].z + b0;
        r1[px0 + 8] = acc[nt].w + b1;
    }
}

// ---------------- launch ----------------
extern "C" void kernel_launch(void* const* d_in, const int* in_sizes, int n_in,
                              void* d_out, int out_size) {
    const float* x           = (const float*)d_in[0];
    const float* offset_feat = (const float*)d_in[1];
    const float* w_off       = (const float*)d_in[2];
    const float* b_off       = (const float*)d_in[3];
    const float* weight      = (const float*)d_in[4];
    const float* bias        = (const float*)d_in[5];
    float* out = (float*)d_out;

    static bool attr_set = false;
    if (!attr_set) {
        cudaFuncSetAttribute(deform_kernel,
                             cudaFuncAttributeMaxDynamicSharedMemorySize,
                             SMU_TOT * 4);
        attr_set = true;
    }

    prep_w_kernel<<<(C_ * 32 * K2_ + 255) / 256, 256>>>(weight);
    nhwc_kernel<<<B_ * H_, 256>>>(x);
    offset_kernel<<<B_ * H_, 128>>>(offset_feat, w_off, b_off);
    deform_kernel<<<B_ * H_ * 2, 128, SMU_TOT * 4>>>(bias, out);
}

// round 16
// speedup vs baseline: 1.2778x; 1.1230x over previous
#include <cuda_runtime.h>
#include <cuda_fp16.h>
#include <math.h>
#include <cstdint>

typedef unsigned long long ull;

// Problem constants
#define B_    4
#define C_    64
#define H_    128
#define W_    128
#define HW_   (H_*W_)
#define OFFC_ 32
#define K2_   9
#define OCOFF 27

// ---------------- scratch ----------------
__device__ int    g_idx[B_ * K2_ * HW_];   // packed clamped corners
__device__ uint4  g_wts[B_ * K2_ * HW_];   // bilinear weights as dup'd half2 x4
__device__ __half g_xth[B_ * HW_ * C_];    // x in NHWC fp16: [b][y][x][c]
// W^T as f16x2 pairs (single fp16): [k][o][36 stride, 32 pairs used]
__device__ uint32_t g_wb[K2_ * C_ * 36];

// ---------------- helpers ----------------
__device__ __forceinline__ uint32_t smem_u32(const void* p) {
    uint32_t a;
    asm("{ .reg .u64 t; cvta.to.shared.u64 t, %1; cvt.u32.u64 %0, t; }" : "=r"(a) : "l"(p));
    return a;
}
__device__ __forceinline__ void ffma2(ull& d, ull a, ull b) {
    asm("fma.rn.f32x2 %0, %1, %2, %0;" : "+l"(d) : "l"(a), "l"(b));
}
__device__ __forceinline__ ull dup2(float s) {
    ull d;
    asm("mov.b64 %0, {%1, %1};" : "=l"(d) : "f"(s));
    return d;
}
__device__ __forceinline__ void mma_f16(float4& d,
                                        uint32_t a0, uint32_t a1, uint32_t a2, uint32_t a3,
                                        uint32_t b0, uint32_t b1) {
    asm volatile(
        "mma.sync.aligned.m16n8k16.row.col.f32.f16.f16.f32 "
        "{%0,%1,%2,%3}, {%4,%5,%6,%7}, {%8,%9}, {%0,%1,%2,%3};"
        : "+f"(d.x), "+f"(d.y), "+f"(d.z), "+f"(d.w)
        : "r"(a0), "r"(a1), "r"(a2), "r"(a3), "r"(b0), "r"(b1));
}
#define LDSM4(r0, r1, r2, r3, addr)                                           \
    asm volatile("ldmatrix.sync.aligned.m8n8.x4.shared.b16 {%0,%1,%2,%3}, [%4];" \
                 : "=r"(r0), "=r"(r1), "=r"(r2), "=r"(r3) : "r"(addr))
__device__ __forceinline__ __half2 u2h(uint32_t u) {
    return *reinterpret_cast<__half2*>(&u);
}
__device__ __forceinline__ uint32_t h2u(__half2 h) {
    return *reinterpret_cast<uint32_t*>(&h);
}

// ---------------- Stage 0: fused x NHWC transpose + weight prep ----------------
// blocks [0,512)   : x NCHW -> NHWC fp16, one (b,y) row each
// blocks [512,584) : weight -> fp16 pairs [k][o][pair], 72 blocks x 256
#define NW_NHWC_BLKS 512
#define NW_W_BLKS    72
#define NW_TOTAL     (NW_NHWC_BLKS + NW_W_BLKS)

__global__ __launch_bounds__(256) void nhwc_w_kernel(
    const float* __restrict__ x,        // [B,64,H,W]
    const float* __restrict__ weight)   // [64,64,3,3]
{
    __shared__ float st[C_ * 129];
    const int blk = blockIdx.x;
    const int tid = threadIdx.x;

    if (blk < NW_NHWC_BLKS) {
        const int y = blk & (H_ - 1);
        const int b = blk >> 7;

        const float* src = x + ((size_t)b * C_ * H_ + y) * W_;
#pragma unroll
        for (int i = 0; i < 8; i++) {
            int idx = tid + i * 256;
            int c   = idx >> 5;
            int x4  = idx & 31;
            float4 v = __ldg((const float4*)(src + (size_t)c * HW_) + x4);
            float* d = st + c * 129 + x4 * 4;
            d[0] = v.x; d[1] = v.y; d[2] = v.z; d[3] = v.w;
        }
        __syncthreads();

        __half* dst = g_xth + ((size_t)(b * H_ + y) * W_) * C_;
#pragma unroll
        for (int i = 0; i < 8; i++) {
            int idx = tid + i * 256;
            int px  = idx >> 4;
            int cq  = idx & 15;
            float v0 = st[(cq * 4 + 0) * 129 + px];
            float v1 = st[(cq * 4 + 1) * 129 + px];
            float v2 = st[(cq * 4 + 2) * 129 + px];
            float v3 = st[(cq * 4 + 3) * 129 + px];
            uint2 o2;
            o2.x = h2u(__floats2half2_rn(v0, v1));
            o2.y = h2u(__floats2half2_rn(v2, v3));
            *(uint2*)(dst + (size_t)px * C_ + cq * 4) = o2;
        }
    } else {
        int i = (blk - NW_NHWC_BLKS) * 256 + tid;
        if (i < C_ * 32 * K2_) {
            int k = i % K2_;
            int t = i / K2_;
            int p = t % 32;
            int o = t / 32;
            float v0 = weight[((size_t)o * C_ + 2 * p)     * K2_ + k];
            float v1 = weight[((size_t)o * C_ + 2 * p + 1) * K2_ + k];
            __half2 h2 = __floats2half2_rn(v0, v1);
            g_wb[((size_t)k * C_ + o) * 36 + p] = h2u(h2);
        }
    }
}

// ---------------- Stage 1: offset conv + bilinear descriptor precompute ----------------
__global__ __launch_bounds__(128) void offset_kernel(
    const float* __restrict__ offset_feat,   // [B,32,H,W]
    const float* __restrict__ w_off,         // [27,32,3,3]
    const float* __restrict__ b_off)         // [27]
{
    __shared__ __align__(16) float s_w[288 * 28];
    __shared__ __align__(16) float s_boff[28];

    const int tid = threadIdx.x;
    const int y   = blockIdx.x & (H_ - 1);
    const int b   = blockIdx.x >> 7;
    const int x   = tid;

    for (int i = tid; i < OCOFF * 288; i += 128) {
        int oc = i / 288;
        int r  = i % 288;
        s_w[r * 28 + oc] = w_off[i];
    }
    if (tid < 28) s_boff[tid] = (tid < OCOFF) ? b_off[tid] : 0.f;
    __syncthreads();

    ull acc2[14];
#pragma unroll
    for (int j = 0; j < 14; j++) acc2[j] = ((const ull*)s_boff)[j];

    const float* fbase = offset_feat + (size_t)b * OFFC_ * HW_;

#pragma unroll
    for (int ky = 0; ky < 3; ky++) {
        const int iy = y - 1 + ky;
        const bool vy = ((unsigned)iy < (unsigned)H_);
#pragma unroll
        for (int kx = 0; kx < 3; kx++) {
            const int ix = x - 1 + kx;
            const bool v = vy && ((unsigned)ix < (unsigned)W_);
            const int tap = ky * 3 + kx;
            const float* ip = fbase + iy * W_ + ix;
#pragma unroll 4
            for (int c = 0; c < OFFC_; c++) {
                float vv = v ? __ldg(ip + c * HW_) : 0.f;
                ull v2 = dup2(vv);
                const ulonglong2* wp = (const ulonglong2*)(s_w + (c * 9 + tap) * 28);
#pragma unroll
                for (int j = 0; j < 7; j++) {
                    ulonglong2 ww = wp[j];
                    ffma2(acc2[2 * j],     ww.x, v2);
                    ffma2(acc2[2 * j + 1], ww.y, v2);
                }
            }
        }
    }

    float acc[28];
#pragma unroll
    for (int j = 0; j < 14; j++) {
        asm("mov.b64 {%0, %1}, %2;" : "=f"(acc[2 * j]), "=f"(acc[2 * j + 1]) : "l"(acc2[j]));
    }

#pragma unroll
    for (int k = 0; k < K2_; k++) {
        float dy = acc[2 * k];
        float dx = acc[2 * k + 1];
        float m  = 1.f / (1.f + __expf(-acc[18 + k]));

        float py = (float)(y - 1 + (k / 3)) + dy;
        float px = (float)(x - 1 + (k % 3)) + dx;
        float y0f = floorf(py), x0f = floorf(px);
        float wy1 = py - y0f,   wx1 = px - x0f;
        float wy0 = 1.f - wy1,  wx0 = 1.f - wx1;
        int y0 = (int)y0f, x0 = (int)x0f;
        int y1 = y0 + 1,   x1 = x0 + 1;

        bool vy0 = ((unsigned)y0 < (unsigned)H_);
        bool vy1 = ((unsigned)y1 < (unsigned)H_);
        bool vx0 = ((unsigned)x0 < (unsigned)W_);
        bool vx1 = ((unsigned)x1 < (unsigned)W_);

        float w00 = wy0 * wx0 * m * (float)(vy0 && vx0);
        float w01 = wy0 * wx1 * m * (float)(vy0 && vx1);
        float w10 = wy1 * wx0 * m * (float)(vy1 && vx0);
        float w11 = wy1 * wx1 * m * (float)(vy1 && vx1);

        int y0c = min(max(y0, 0), H_ - 1);
        int y1c = min(max(y1, 0), H_ - 1);
        int x0c = min(max(x0, 0), W_ - 1);
        int x1c = min(max(x1, 0), W_ - 1);

        int base = ((b * K2_ + k) * H_ + y) * W_ + x;
        g_idx[base] = (y0c << 24) | (y1c << 16) | (x0c << 8) | x1c;
        uint4 wq;
        wq.x = h2u(__float2half2_rn(w00));
        wq.y = h2u(__float2half2_rn(w01));
        wq.z = h2u(__float2half2_rn(w10));
        wq.w = h2u(__float2half2_rn(w11));
        g_wts[base] = wq;
    }
}

// ---------------- Stage 2: software-pipelined fill + mma.sync fp16 ----------------
// block = half a (b,y) row (64 px), 4 warps; warp w owns px strip [16w,16w+16).
// grid 1024, 4 CTAs/SM. Iter k:
//   barrier -> fill-LDGs g0 (regs) -> GEMM kt0,1 -> fill-compute g0 + LDGs g1
//   -> GEMM kt2,3 -> fill-compute g1 -> copyB(k+1)
// Corner-load latency drains under the mma stream instead of preceding it.
// smem u32: A0 2304  A1 2304  B0 2304  B1 2304  sDw uint4[576]=2304  sDi 576
#define SMU_A0  0
#define SMU_A1  2304
#define SMU_B0  4608
#define SMU_B1  6912
#define SMU_DW  9216
#define SMU_DI  11520
#define SMU_TOT 12096     // * 4 = 48384 bytes

__global__ __launch_bounds__(128, 4) void deform_kernel(
    const float* __restrict__ bias,  // [64]
    float* __restrict__ out)         // [B,64,H,W]
{
    extern __shared__ uint32_t usm[];
    const uint4* sDw = (const uint4*)(usm + SMU_DW);
    const int*   sDi = (const int*)(usm + SMU_DI);

    const int tid  = threadIdx.x;
    const int wid  = tid >> 5;
    const int lid  = tid & 31;
    const int half = blockIdx.x & 1;
    const int y    = (blockIdx.x >> 1) & (H_ - 1);
    const int b    = blockIdx.x >> 8;

    const int pxw = wid * 16;         // local strip base (0..48)
    const int g   = lid >> 2;
    const int tg  = lid & 3;
    const int c4  = lid & 15;
    const int jof = lid >> 4;         // 0/1 pixel parity within fill task

    const uint32_t smb = smem_u32(usm);
    const int t8 = lid >> 3, r8 = lid & 7;
    const uint32_t aRow = 4u * ((uint32_t)(pxw + (t8 & 1) * 8 + r8) * 36u
                                + (uint32_t)(t8 >> 1) * 4u);
    const uint32_t aBase0 = smb + 4u * SMU_A0 + aRow;
    const uint32_t aBase1 = smb + 4u * SMU_A1 + aRow;
    const uint32_t bRow = 4u * ((uint32_t)((t8 >> 1) * 8 + r8) * 36u
                                + (uint32_t)(t8 & 1) * 4u);
    const uint32_t bBase0 = smb + 4u * SMU_B0 + bRow;
    const uint32_t bBase1 = smb + 4u * SMU_B1 + bRow;

    float4 acc[8];
#pragma unroll
    for (int nt = 0; nt < 8; nt++) acc[nt] = make_float4(0.f, 0.f, 0.f, 0.f);

    const __half* xtb = g_xth + (size_t)b * HW_ * C_;

    // ---- prologue: stage descriptors + copy B(0) ----
    {
        const int rowbase = (b * K2_ * H_ + y) * W_ + half * 64;
        uint4* dDw = (uint4*)(usm + SMU_DW);
        int*   dDi = (int*)(usm + SMU_DI);
#pragma unroll
        for (int it = 0; it < 5; it++) {
            int i = tid + it * 128;
            if (i < K2_ * 64) {
                int k  = i >> 6;
                int xx = i & 63;
                int src = rowbase + k * HW_ + xx;
                dDw[i] = __ldg(&g_wts[src]);
                dDi[i] = __ldg(&g_idx[src]);
            }
        }
        const float4* srcB = (const float4*)g_wb;
        float4* dstB = (float4*)(usm + SMU_B0);
#pragma unroll
        for (int it = 0; it < 5; it++) {
            int i = tid + it * 128;
            if (i < 576) dstB[i] = __ldg(srcB + i);
        }
    }
    __syncthreads();

    // ---- fill(0) into A0 (latency exposed once) ----
#pragma unroll
    for (int j = 0; j < 8; j++) {
        const int pxl = pxw + 2 * j + jof;
        const uint4 wq = sDw[pxl];
        const int   di = sDi[pxl];
        const int y0c = (di >> 24) & 255, y1c = (di >> 16) & 255;
        const int x0c = (di >> 8) & 255,  x1c = di & 255;
        const uint2 c00 = __ldg((const uint2*)(xtb + (size_t)(y0c * W_ + x0c) * C_) + c4);
        const uint2 c01 = __ldg((const uint2*)(xtb + (size_t)(y0c * W_ + x1c) * C_) + c4);
        const uint2 c10 = __ldg((const uint2*)(xtb + (size_t)(y1c * W_ + x0c) * C_) + c4);
        const uint2 c11 = __ldg((const uint2*)(xtb + (size_t)(y1c * W_ + x1c) * C_) + c4);
        __half2 s01 = __hmul2(u2h(c00.x), u2h(wq.x));
        s01 = __hfma2(u2h(c01.x), u2h(wq.y), s01);
        s01 = __hfma2(u2h(c10.x), u2h(wq.z), s01);
        s01 = __hfma2(u2h(c11.x), u2h(wq.w), s01);
        __half2 s23 = __hmul2(u2h(c00.y), u2h(wq.x));
        s23 = __hfma2(u2h(c01.y), u2h(wq.y), s23);
        s23 = __hfma2(u2h(c10.y), u2h(wq.z), s23);
        s23 = __hfma2(u2h(c11.y), u2h(wq.w), s23);
        *(uint2*)&usm[SMU_A0 + pxl * 36 + 2 * c4] = make_uint2(h2u(s01), h2u(s23));
    }

#pragma unroll 1
    for (int k = 0; k < K2_; k++) {
        // barrier: fill(k)/B(k) visible; GEMM(k-1) done -> buffers (k+1)&1 free
        __syncthreads();

        const uint32_t aB = (k & 1) ? aBase1 : aBase0;
        const uint32_t bB = (k & 1) ? bBase1 : bBase0;
        const bool has_next = (k + 1 < K2_);
        uint32_t* sAn = usm + (((k + 1) & 1) ? SMU_A1 : SMU_A0);
        const int dnext = (k + 1) * 64;

        uint2 q00[4], q01[4], q10[4], q11[4];

        // ---- fill-LDGs group 0 (j = 0..3) ----
        if (has_next) {
#pragma unroll
            for (int j = 0; j < 4; j++) {
                const int pxl = pxw + 2 * j + jof;
                const int di = sDi[dnext + pxl];
                const int y0c = (di >> 24) & 255, y1c = (di >> 16) & 255;
                const int x0c = (di >> 8) & 255,  x1c = di & 255;
                q00[j] = __ldg((const uint2*)(xtb + (size_t)(y0c * W_ + x0c) * C_) + c4);
                q01[j] = __ldg((const uint2*)(xtb + (size_t)(y0c * W_ + x1c) * C_) + c4);
                q10[j] = __ldg((const uint2*)(xtb + (size_t)(y1c * W_ + x0c) * C_) + c4);
                q11[j] = __ldg((const uint2*)(xtb + (size_t)(y1c * W_ + x1c) * C_) + c4);
            }
        }

        // ---- GEMM(k) kt 0,1 ----
#pragma unroll
        for (int kt = 0; kt < 2; kt++) {
            uint32_t a0, a1, a2, a3;
            LDSM4(a0, a1, a2, a3, aB + kt * 32u);
#pragma unroll
            for (int np = 0; np < 4; np++) {
                uint32_t b0, b1, b2, b3;
                LDSM4(b0, b1, b2, b3, bB + (uint32_t)np * 2304u + kt * 32u);
                mma_f16(acc[2 * np],     a0, a1, a2, a3, b0, b1);
                mma_f16(acc[2 * np + 1], a0, a1, a2, a3, b2, b3);
            }
        }

        if (has_next) {
            // ---- fill-compute/STS group 0 ----
#pragma unroll
            for (int j = 0; j < 4; j++) {
                const int pxl = pxw + 2 * j + jof;
                const uint4 wq = sDw[dnext + pxl];
                __half2 s01 = __hmul2(u2h(q00[j].x), u2h(wq.x));
                s01 = __hfma2(u2h(q01[j].x), u2h(wq.y), s01);
                s01 = __hfma2(u2h(q10[j].x), u2h(wq.z), s01);
                s01 = __hfma2(u2h(q11[j].x), u2h(wq.w), s01);
                __half2 s23 = __hmul2(u2h(q00[j].y), u2h(wq.x));
                s23 = __hfma2(u2h(q01[j].y), u2h(wq.y), s23);
                s23 = __hfma2(u2h(q10[j].y), u2h(wq.z), s23);
                s23 = __hfma2(u2h(q11[j].y), u2h(wq.w), s23);
                *(uint2*)&sAn[pxl * 36 + 2 * c4] = make_uint2(h2u(s01), h2u(s23));
            }
            // ---- fill-LDGs group 1 (j = 4..7) ----
#pragma unroll
            for (int j = 0; j < 4; j++) {
                const int pxl = pxw + 2 * (j + 4) + jof;
                const int di = sDi[dnext + pxl];
                const int y0c = (di >> 24) & 255, y1c = (di >> 16) & 255;
                const int x0c = (di >> 8) & 255,  x1c = di & 255;
                q00[j] = __ldg((const uint2*)(xtb + (size_t)(y0c * W_ + x0c) * C_) + c4);
                q01[j] = __ldg((const uint2*)(xtb + (size_t)(y0c * W_ + x1c) * C_) + c4);
                q10[j] = __ldg((const uint2*)(xtb + (size_t)(y1c * W_ + x0c) * C_) + c4);
                q11[j] = __ldg((const uint2*)(xtb + (size_t)(y1c * W_ + x1c) * C_) + c4);
            }
        }

        // ---- GEMM(k) kt 2,3 ----
#pragma unroll
        for (int kt = 2; kt < 4; kt++) {
            uint32_t a0, a1, a2, a3;
            LDSM4(a0, a1, a2, a3, aB + kt * 32u);
#pragma unroll
            for (int np = 0; np < 4; np++) {
                uint32_t b0, b1, b2, b3;
                LDSM4(b0, b1, b2, b3, bB + (uint32_t)np * 2304u + kt * 32u);
                mma_f16(acc[2 * np],     a0, a1, a2, a3, b0, b1);
                mma_f16(acc[2 * np + 1], a0, a1, a2, a3, b2, b3);
            }
        }

        if (has_next) {
            // ---- fill-compute/STS group 1 ----
#pragma unroll
            for (int j = 0; j < 4; j++) {
                const int pxl = pxw + 2 * (j + 4) + jof;
                const uint4 wq = sDw[dnext + pxl];
                __half2 s01 = __hmul2(u2h(q00[j].x), u2h(wq.x));
                s01 = __hfma2(u2h(q01[j].x), u2h(wq.y), s01);
                s01 = __hfma2(u2h(q10[j].x), u2h(wq.z), s01);
                s01 = __hfma2(u2h(q11[j].x), u2h(wq.w), s01);
                __half2 s23 = __hmul2(u2h(q00[j].y), u2h(wq.x));
                s23 = __hfma2(u2h(q01[j].y), u2h(wq.y), s23);
                s23 = __hfma2(u2h(q10[j].y), u2h(wq.z), s23);
                s23 = __hfma2(u2h(q11[j].y), u2h(wq.w), s23);
                *(uint2*)&sAn[pxl * 36 + 2 * c4] = make_uint2(h2u(s01), h2u(s23));
            }
            // ---- cooperative copy of B(k+1) (latency absorbed by barrier) ----
            const float4* src = (const float4*)(g_wb + (size_t)(k + 1) * 2304);
            float4* dst = (float4*)(usm + (((k + 1) & 1) ? SMU_B1 : SMU_B0));
#pragma unroll
            for (int it = 0; it < 5; it++) {
                int i = tid + it * 128;
                if (i < 576) dst[i] = __ldg(src + i);
            }
        }
    }

    // ---- epilogue ----
    const int px0 = half * 64 + pxw + g;
#pragma unroll
    for (int nt = 0; nt < 8; nt++) {
        const int o = nt * 8 + 2 * tg;
        const float b0 = __ldg(&bias[o]);
        const float b1 = __ldg(&bias[o + 1]);
        float* r0 = out + (((size_t)b * C_ + o)     * H_ + y) * W_;
        float* r1 = out + (((size_t)b * C_ + o + 1) * H_ + y) * W_;
        r0[px0]     = acc[nt].x + b0;
        r1[px0]     = acc[nt].y + b1;
        r0[px0 + 8] = acc[nt].z + b0;
        r1[px0 + 8] = acc[nt].w + b1;
    }
}

// ---------------- launch ----------------
extern "C" void kernel_launch(void* const* d_in, const int* in_sizes, int n_in,
                              void* d_out, int out_size) {
    const float* x           = (const float*)d_in[0];
    const float* offset_feat = (const float*)d_in[1];
    const float* w_off       = (const float*)d_in[2];
    const float* b_off       = (const float*)d_in[3];
    const float* weight      = (const float*)d_in[4];
    const float* bias        = (const float*)d_in[5];
    float* out = (float*)d_out;

    static bool attr_set = false;
    if (!attr_set) {
        cudaFuncSetAttribute(deform_kernel,
                             cudaFuncAttributeMaxDynamicSharedMemorySize,
                             SMU_TOT * 4);
        attr_set = true;
    }

    nhwc_w_kernel<<<NW_TOTAL, 256>>>(x, weight);
    offset_kernel<<<B_ * H_, 128>>>(offset_feat, w_off, b_off);
    deform_kernel<<<B_ * H_ * 2, 128, SMU_TOT * 4>>>(bias, out);
}